// round 6
// baseline (speedup 1.0000x reference)
#include <cuda_runtime.h>
#include <cuda_fp16.h>
#include <cstdint>

// ============================================================
// Bahdanau additive attention, GB300 sm_103 (baseline PTX only)
//   dp[b,e]  = dec[b]@w2 + b2 + b1
//   scores   = v . tanh(enc@w1 + dp)     (fused HMMA mma.sync GEMM epilogue)
//   attn     = softmax_s(scores)         (bv dropped: shift-invariant)
//   context  = attn @ enc                (fp16 enc)
// ============================================================

#define ENCD 1024
#define NB   32
#define NS   2048
#define MTOT (NB*NS)

// GEMM tile: BM=128, BN=128, BK=64, 3-stage cp.async, 128 thr (4 warps 2x2),
// warp tile 64x64 (halves LDS bytes/MAC vs 32x64)
#define STAGE_BYTES 32768          // A 16KB + B 16KB
#define MISC_OFF    (3*STAGE_BYTES)
#define SMEM_REQ    (MISC_OFF + 2048)
#define NPART 16                   // 8 nt * 2 warp_n partial score slots

// ---------------- device scratch ----------------
__device__ __half g_encH[(size_t)MTOT*ENCD];      // enc fp16, 128MB
__device__ __half g_w1H[(size_t)ENCD*ENCD];       // w1 transposed: [e][d]
__device__ float  g_dp[NB*ENCD];
__device__ float  g_scores_part[NPART][MTOT];     // 4MB
__device__ float  g_attn[NB*NS];
__device__ float  g_ctx_part[16][NB*ENCD];

// ---------------- helpers ----------------
__device__ __forceinline__ uint32_t smem_u32(const void* p) {
    uint32_t a;
    asm("{ .reg .u64 t; cvta.to.shared.u64 t, %1; cvt.u32.u64 %0, t; }" : "=r"(a) : "l"(p));
    return a;
}
#define SWZ128(off) ((off) ^ (((off) >> 3) & 0x70))

__device__ __forceinline__ void cp_async16(uint32_t dst, const void* src) {
    asm volatile("cp.async.cg.shared.global [%0], [%1], 16;" :: "r"(dst), "l"(src) : "memory");
}
#define CP_COMMIT() asm volatile("cp.async.commit_group;" ::: "memory")
#define CP_WAIT1()  asm volatile("cp.async.wait_group 1;" ::: "memory")

__device__ __forceinline__ void ldsm_x4(uint32_t* r, uint32_t addr) {
    asm volatile("ldmatrix.sync.aligned.m8n8.x4.shared.b16 {%0,%1,%2,%3}, [%4];"
                 : "=r"(r[0]), "=r"(r[1]), "=r"(r[2]), "=r"(r[3]) : "r"(addr));
}
__device__ __forceinline__ void mma16816(float* c, const uint32_t* a, const uint32_t* b) {
    asm volatile(
        "mma.sync.aligned.m16n8k16.row.col.f32.f16.f16.f32 "
        "{%0,%1,%2,%3}, {%4,%5,%6,%7}, {%8,%9}, {%0,%1,%2,%3};"
        : "+f"(c[0]), "+f"(c[1]), "+f"(c[2]), "+f"(c[3])
        : "r"(a[0]), "r"(a[1]), "r"(a[2]), "r"(a[3]), "r"(b[0]), "r"(b[1]));
}

// ============================================================
// 1a. enc fp32 -> fp16
// ============================================================
__global__ void conv_enc_kernel(const float* __restrict__ enc) {
    const float4* in4 = (const float4*)enc;
    uint4* out4 = (uint4*)g_encH;
    int base = blockIdx.x * 256 + threadIdx.x;           // 8192 blocks
    #pragma unroll
    for (int it = 0; it < 4; it++) {
        int o = base + it * 2097152;                     // 8388608 uint4 outs
        float4 a = in4[2 * o];
        float4 b = in4[2 * o + 1];
        __half2 h0 = __floats2half2_rn(a.x, a.y);
        __half2 h1 = __floats2half2_rn(a.z, a.w);
        __half2 h2 = __floats2half2_rn(b.x, b.y);
        __half2 h3 = __floats2half2_rn(b.z, b.w);
        uint4 r;
        r.x = *(const uint32_t*)&h0; r.y = *(const uint32_t*)&h1;
        r.z = *(const uint32_t*)&h2; r.w = *(const uint32_t*)&h3;
        out4[o] = r;
    }
}

// ============================================================
// 1b. w1 transpose -> fp16   g_w1H[e][d] = w1[d][e]
// ============================================================
__global__ void conv_w1_kernel(const float* __restrict__ w1) {
    __shared__ float tile[32][33];
    int dt = blockIdx.x * 32, et = blockIdx.y * 32;
    int tx = threadIdx.x, ty = threadIdx.y;               // 32x8
    #pragma unroll
    for (int i = 0; i < 4; i++)
        tile[ty + i * 8][tx] = w1[(dt + ty + i * 8) * 1024 + et + tx];
    __syncthreads();
    #pragma unroll
    for (int i = 0; i < 4; i++)
        g_w1H[(et + ty + i * 8) * 1024 + dt + tx] = __float2half(tile[tx][ty + i * 8]);
}

// ============================================================
// 2. dp[b][e] = dec[b]@w2 + b2[e] + b1[e]
// ============================================================
__global__ void dp_kernel(const float* __restrict__ dec, const float* __restrict__ w2,
                          const float* __restrict__ b1, const float* __restrict__ b2) {
    __shared__ float dec_s[1024];
    int b  = blockIdx.x >> 3;
    int eb = blockIdx.x & 7;
    int t  = threadIdx.x;       // 128
    #pragma unroll
    for (int i = 0; i < 8; i++) dec_s[t + i * 128] = dec[b * 1024 + t + i * 128];
    __syncthreads();
    int e = eb * 128 + t;
    float acc = 0.f;
    #pragma unroll 8
    for (int d = 0; d < 1024; d++)
        acc += dec_s[d] * w2[d * 1024 + e];
    g_dp[b * 1024 + e] = acc + b1[e] + b2[e];
}

// ============================================================
// 3. Fused GEMM + tanh + v-dot
//    mma.sync fp16, cp.async 3-stage, single barrier per stage,
//    4 warps, warp tile 64x64 (LDS-traffic-optimal), frag parity buffers
//    grid: 512 mt x 8 nt ; block 128
// ============================================================
__global__ void __launch_bounds__(128, 2)
gemm_kernel(const float* __restrict__ v) {
    extern __shared__ char sm[];
    uint32_t smb = smem_u32(sm);

    const int tid = threadIdx.x;
    const int lane = tid & 31, wid = tid >> 5;
    const int warp_m = wid >> 1, warp_n = wid & 1;        // 2 x 2
    const int mt = blockIdx.x >> 3;                        // 512
    const int nt = blockIdx.x & 7;                         // 8
    const int b  = mt >> 4;

    float* dp_s = (float*)(sm + MISC_OFF);
    float* v_s  = (float*)(sm + MISC_OFF + 512);
    dp_s[tid] = g_dp[b * 1024 + nt * 128 + tid];
    v_s[tid]  = v[nt * 128 + tid];

    const int arow = mt * 128;
    const int brow = nt * 128;

    // cp.async: thread tid owns row tid (A and B), 8 chunks of 16B each
    // prologue: stages 0,1
    #pragma unroll
    for (int s = 0; s < 2; s++) {
        uint32_t st = smb + s * STAGE_BYTES;
        #pragma unroll
        for (int c = 0; c < 8; c++) {
            uint32_t off = SWZ128((uint32_t)(tid * 128 + c * 16));
            cp_async16(st + off,         &g_encH[(size_t)(arow + tid) * 1024 + s * 64 + c * 8]);
            cp_async16(st + 16384 + off, &g_w1H[(size_t)(brow + tid) * 1024 + s * 64 + c * 8]);
        }
        CP_COMMIT();
    }

    float acc[4][8][4];     // [m16 tile][n8 tile][regs] = 128 regs
    #pragma unroll
    for (int t = 0; t < 4; t++)
        #pragma unroll
        for (int j = 0; j < 8; j++)
            #pragma unroll
            for (int q = 0; q < 4; q++) acc[t][j][q] = 0.f;

    // ldmatrix lane addressing
    const int l15 = lane & 15, lh = lane >> 4;                       // A x4
    const int bn_row  = (lane & 7) + ((lane >> 4) << 3);             // B x4: row in n16
    const int bk_half = (lane >> 3) & 1;                             // B x4: k-half

    uint32_t afr[2][4][4];   // [kk-parity][m16 tile][regs]
    uint32_t bfr[2][4];      // [u-parity][regs] = n16 x k16

#define LD_A1(par, kk, t)                                                                          \
        ldsm_x4(afr[par][t], Ast + SWZ128((uint32_t)((warp_m * 64 + (t) * 16 + l15) * 128 + (kk) * 32 + lh * 16)))
#define LD_B1(par, kk, q)                                                                          \
        ldsm_x4(bfr[par], Bst + SWZ128((uint32_t)((warp_n * 64 + (q) * 16 + bn_row) * 128 + (kk) * 32 + bk_half * 16)))

    #pragma unroll 1
    for (int ks = 0; ks < 16; ks++) {
        CP_WAIT1();
        __syncthreads();   // single barrier per stage (prefetch dist 2 over 3 bufs)

        if (ks + 2 < 16) {
            const int s = ks + 2;
            uint32_t st = smb + (s % 3) * STAGE_BYTES;
            #pragma unroll
            for (int c = 0; c < 8; c++) {
                uint32_t off = SWZ128((uint32_t)(tid * 128 + c * 16));
                cp_async16(st + off,         &g_encH[(size_t)(arow + tid) * 1024 + s * 64 + c * 8]);
                cp_async16(st + 16384 + off, &g_w1H[(size_t)(brow + tid) * 1024 + s * 64 + c * 8]);
            }
        }
        CP_COMMIT();

        uint32_t Ast = smb + (ks % 3) * STAGE_BYTES;
        uint32_t Bst = Ast + 16384;

        // preload kk=0 fragments
        LD_A1(0, 0, 0); LD_A1(0, 0, 1); LD_A1(0, 0, 2); LD_A1(0, 0, 3);
        LD_B1(0, 0, 0);
        #pragma unroll
        for (int u = 0; u < 16; u++) {
            const int kk = u >> 2, q = u & 3;
            // prefetch next B frag (next u) and spread A prefetch (1 per u) for next kk
            if (u < 15) LD_B1((u + 1) & 1, (u + 1) >> 2, (u + 1) & 3);
            if (kk < 3) LD_A1((kk + 1) & 1, kk + 1, q);
            const int p = kk & 1, pb = u & 1;
            #pragma unroll
            for (int t = 0; t < 4; t++) {
                mma16816(acc[t][2 * q],     afr[p][t], bfr[pb]);
                mma16816(acc[t][2 * q + 1], afr[p][t], bfr[pb] + 2);
            }
        }
    }
#undef LD_A1
#undef LD_B1

    // fused epilogue: per-row sum of v[n]*tanh(acc + dp[n])
    #pragma unroll
    for (int t = 0; t < 4; t++) {
        float rs0 = 0.f, rs1 = 0.f;     // rows m_base, m_base+8
        #pragma unroll
        for (int j = 0; j < 8; j++) {
            int nl = warp_n * 64 + j * 8 + (lane & 3) * 2;
            float d0 = dp_s[nl], d1 = dp_s[nl + 1];
            float v0 = v_s[nl],  v1 = v_s[nl + 1];
            float y0, y1, y2, y3;
            asm("tanh.approx.f32 %0, %1;" : "=f"(y0) : "f"(acc[t][j][0] + d0));
            asm("tanh.approx.f32 %0, %1;" : "=f"(y1) : "f"(acc[t][j][1] + d1));
            asm("tanh.approx.f32 %0, %1;" : "=f"(y2) : "f"(acc[t][j][2] + d0));
            asm("tanh.approx.f32 %0, %1;" : "=f"(y3) : "f"(acc[t][j][3] + d1));
            rs0 += v0 * y0 + v1 * y1;
            rs1 += v0 * y2 + v1 * y3;
        }
        rs0 += __shfl_xor_sync(~0u, rs0, 1); rs0 += __shfl_xor_sync(~0u, rs0, 2);
        rs1 += __shfl_xor_sync(~0u, rs1, 1); rs1 += __shfl_xor_sync(~0u, rs1, 2);
        if ((lane & 3) == 0) {
            int m = mt * 128 + warp_m * 64 + t * 16 + (lane >> 2);
            int p = nt * 2 + warp_n;
            g_scores_part[p][m]     = rs0;
            g_scores_part[p][m + 8] = rs1;
        }
    }
}

// ============================================================
// 4. softmax over sequence dim (per batch)
// ============================================================
__global__ void softmax_kernel() {
    __shared__ float red[32];
    __shared__ float stat[2];
    int bq = blockIdx.x;
    int t = threadIdx.x, lane = t & 31, wid = t >> 5;   // 1024 threads
    int base = bq * 2048;
    float s0 = 0.f, s1 = 0.f;
    #pragma unroll
    for (int p = 0; p < NPART; p++) {
        s0 += g_scores_part[p][base + t];
        s1 += g_scores_part[p][base + 1024 + t];
    }
    float mx = fmaxf(s0, s1);
    #pragma unroll
    for (int o = 16; o > 0; o >>= 1) mx = fmaxf(mx, __shfl_xor_sync(~0u, mx, o));
    if (lane == 0) red[wid] = mx;
    __syncthreads();
    if (t < 32) {
        float m2 = red[t];
        #pragma unroll
        for (int o = 16; o > 0; o >>= 1) m2 = fmaxf(m2, __shfl_xor_sync(~0u, m2, o));
        if (t == 0) stat[0] = m2;
    }
    __syncthreads();
    float M = stat[0];
    float e0 = __expf(s0 - M), e1 = __expf(s1 - M);
    float sum = e0 + e1;
    #pragma unroll
    for (int o = 16; o > 0; o >>= 1) sum += __shfl_xor_sync(~0u, sum, o);
    if (lane == 0) red[wid] = sum;
    __syncthreads();
    if (t < 32) {
        float z = red[t];
        #pragma unroll
        for (int o = 16; o > 0; o >>= 1) z += __shfl_xor_sync(~0u, z, o);
        if (t == 0) stat[1] = z;
    }
    __syncthreads();
    float inv = 1.f / stat[1];
    g_attn[base + t]        = e0 * inv;
    g_attn[base + 1024 + t] = e1 * inv;
}

// ============================================================
// 5. context partials over s-chunks (fp16 enc, half2 loads)
// ============================================================
__global__ void context_kernel() {
    __shared__ float attn_s[128];
    int sc = blockIdx.x, eb = blockIdx.y, b = blockIdx.z;   // 16 x 4 x 32
    int t = threadIdx.x;                  // 128
    attn_s[t] = g_attn[b * 2048 + sc * 128 + t];
    __syncthreads();
    int e2 = eb * 256 + 2 * t;            // even element index
    const __half2* base = (const __half2*)g_encH
        + ((size_t)(b * 2048 + sc * 128) * 1024 + e2) / 2;
    float acc0 = 0.f, acc1 = 0.f;
    #pragma unroll 4
    for (int s = 0; s < 128; s++) {
        __half2 h = base[(size_t)s * 512];
        float2 f = __half22float2(h);
        acc0 += attn_s[s] * f.x;
        acc1 += attn_s[s] * f.y;
    }
    g_ctx_part[sc][b * 1024 + e2]     = acc0;
    g_ctx_part[sc][b * 1024 + e2 + 1] = acc1;
}

// ============================================================
// 6. final reduce -> d_out [32,1024] fp32
// ============================================================
__global__ void reduce_kernel(float* __restrict__ out) {
    int i = blockIdx.x * 256 + threadIdx.x;   // 128 x 256
    float acc = 0.f;
    #pragma unroll
    for (int sc = 0; sc < 16; sc++) acc += g_ctx_part[sc][i];
    out[i] = acc;
}

// ============================================================
extern "C" void kernel_launch(void* const* d_in, const int* in_sizes, int n_in,
                              void* d_out, int out_size) {
    const float* enc = (const float*)d_in[0];
    const float* dec = (const float*)d_in[1];
    const float* w1  = (const float*)d_in[2];
    const float* b1  = (const float*)d_in[3];
    const float* w2  = (const float*)d_in[4];
    const float* b2  = (const float*)d_in[5];
    const float* v   = (const float*)d_in[6];
    // bv (d_in[7]) unused: softmax is shift-invariant.
    float* out = (float*)d_out;

    cudaFuncSetAttribute(gemm_kernel, cudaFuncAttributeMaxDynamicSharedMemorySize, SMEM_REQ);

    conv_enc_kernel<<<8192, 256>>>(enc);
    conv_w1_kernel<<<dim3(32, 32), dim3(32, 8)>>>(w1);
    dp_kernel<<<256, 128>>>(dec, w2, b1, b2);
    gemm_kernel<<<4096, 128, SMEM_REQ>>>(v);
    softmax_kernel<<<32, 1024>>>();
    context_kernel<<<dim3(16, 4, 32), 128>>>();
    reduce_kernel<<<128, 256>>>(out);
}

// round 7
// speedup vs baseline: 1.3744x; 1.3744x over previous
#include <cuda_runtime.h>
#include <cuda_fp16.h>
#include <cstdint>

// ============================================================
// Bahdanau additive attention, GB300 sm_103 (baseline PTX only)
//   dp[b,e]  = dec[b]@w2 + b2 + b1
//   scores   = v . tanh(enc@w1 + dp)     (fused HMMA mma.sync GEMM epilogue)
//   attn     = softmax_s(scores)         (bv dropped: shift-invariant)
//   context  = attn @ enc                (fp16 enc)
// ============================================================

#define ENCD 1024
#define NB   32
#define NS   2048
#define MTOT (NB*NS)

// GEMM tile: BM=128, BN=128, BK=64, 3-stage cp.async, 256 thr (8 warps 4x2)
#define STAGE_BYTES 32768          // A 16KB + B 16KB
#define MISC_OFF    (3*STAGE_BYTES)
#define SMEM_REQ    (MISC_OFF + 2048)
#define NPART 16                   // 8 nt * 2 warp_n partial score slots

// ---------------- device scratch ----------------
__device__ __half g_encH[(size_t)MTOT*ENCD];      // enc fp16, 128MB
__device__ __half g_w1H[(size_t)ENCD*ENCD];       // w1 transposed: [e][d]
__device__ float  g_dp[NB*ENCD];
__device__ float  g_scores_part[NPART][MTOT];     // 4MB
__device__ float  g_attn[NB*NS];
__device__ float  g_ctx_part[16][NB*ENCD];

// ---------------- helpers ----------------
__device__ __forceinline__ uint32_t smem_u32(const void* p) {
    uint32_t a;
    asm("{ .reg .u64 t; cvta.to.shared.u64 t, %1; cvt.u32.u64 %0, t; }" : "=r"(a) : "l"(p));
    return a;
}
#define SWZ128(off) ((off) ^ (((off) >> 3) & 0x70))

__device__ __forceinline__ void cp_async16(uint32_t dst, const void* src) {
    asm volatile("cp.async.cg.shared.global [%0], [%1], 16;" :: "r"(dst), "l"(src) : "memory");
}
#define CP_COMMIT() asm volatile("cp.async.commit_group;" ::: "memory")
#define CP_WAIT1()  asm volatile("cp.async.wait_group 1;" ::: "memory")

__device__ __forceinline__ void ldsm_x4(uint32_t* r, uint32_t addr) {
    asm volatile("ldmatrix.sync.aligned.m8n8.x4.shared.b16 {%0,%1,%2,%3}, [%4];"
                 : "=r"(r[0]), "=r"(r[1]), "=r"(r[2]), "=r"(r[3]) : "r"(addr));
}
__device__ __forceinline__ void mma16816(float* c, const uint32_t* a, const uint32_t* b) {
    asm volatile(
        "mma.sync.aligned.m16n8k16.row.col.f32.f16.f16.f32 "
        "{%0,%1,%2,%3}, {%4,%5,%6,%7}, {%8,%9}, {%0,%1,%2,%3};"
        : "+f"(c[0]), "+f"(c[1]), "+f"(c[2]), "+f"(c[3])
        : "r"(a[0]), "r"(a[1]), "r"(a[2]), "r"(a[3]), "r"(b[0]), "r"(b[1]));
}

// ============================================================
// 1a. enc fp32 -> fp16
// ============================================================
__global__ void conv_enc_kernel(const float* __restrict__ enc) {
    const float4* in4 = (const float4*)enc;
    uint4* out4 = (uint4*)g_encH;
    int base = blockIdx.x * 256 + threadIdx.x;           // 8192 blocks
    #pragma unroll
    for (int it = 0; it < 4; it++) {
        int o = base + it * 2097152;                     // 8388608 uint4 outs
        float4 a = in4[2 * o];
        float4 b = in4[2 * o + 1];
        __half2 h0 = __floats2half2_rn(a.x, a.y);
        __half2 h1 = __floats2half2_rn(a.z, a.w);
        __half2 h2 = __floats2half2_rn(b.x, b.y);
        __half2 h3 = __floats2half2_rn(b.z, b.w);
        uint4 r;
        r.x = *(const uint32_t*)&h0; r.y = *(const uint32_t*)&h1;
        r.z = *(const uint32_t*)&h2; r.w = *(const uint32_t*)&h3;
        out4[o] = r;
    }
}

// ============================================================
// 1b. w1 transpose -> fp16   g_w1H[e][d] = w1[d][e]
// ============================================================
__global__ void conv_w1_kernel(const float* __restrict__ w1) {
    __shared__ float tile[32][33];
    int dt = blockIdx.x * 32, et = blockIdx.y * 32;
    int tx = threadIdx.x, ty = threadIdx.y;               // 32x8
    #pragma unroll
    for (int i = 0; i < 4; i++)
        tile[ty + i * 8][tx] = w1[(dt + ty + i * 8) * 1024 + et + tx];
    __syncthreads();
    #pragma unroll
    for (int i = 0; i < 4; i++)
        g_w1H[(et + ty + i * 8) * 1024 + dt + tx] = __float2half(tile[tx][ty + i * 8]);
}

// ============================================================
// 2. dp[b][e] = dec[b]@w2 + b2[e] + b1[e]
// ============================================================
__global__ void dp_kernel(const float* __restrict__ dec, const float* __restrict__ w2,
                          const float* __restrict__ b1, const float* __restrict__ b2) {
    __shared__ float dec_s[1024];
    int b  = blockIdx.x >> 3;
    int eb = blockIdx.x & 7;
    int t  = threadIdx.x;       // 128
    #pragma unroll
    for (int i = 0; i < 8; i++) dec_s[t + i * 128] = dec[b * 1024 + t + i * 128];
    __syncthreads();
    int e = eb * 128 + t;
    float acc = 0.f;
    #pragma unroll 8
    for (int d = 0; d < 1024; d++)
        acc += dec_s[d] * w2[d * 1024 + e];
    g_dp[b * 1024 + e] = acc + b1[e] + b2[e];
}

// ============================================================
// 3. Fused GEMM + tanh + v-dot
//    mma.sync fp16, cp.async 3-stage, single barrier per stage,
//    B-fragment prefetch distance 2 (covers LDS latency), A distance 4 units
//    grid: 512 mt x 8 nt ; block 256 (8 warps, 4m x 2n, warp tile 32x64)
// ============================================================
__global__ void __launch_bounds__(256, 2)
gemm_kernel(const float* __restrict__ v) {
    extern __shared__ char sm[];
    uint32_t smb = smem_u32(sm);

    const int tid = threadIdx.x;
    const int lane = tid & 31, wid = tid >> 5;
    const int warp_m = wid >> 1, warp_n = wid & 1;        // 4 x 2
    const int mt = blockIdx.x >> 3;                        // 512
    const int nt = blockIdx.x & 7;                         // 8
    const int b  = mt >> 4;

    float* dp_s = (float*)(sm + MISC_OFF);
    float* v_s  = (float*)(sm + MISC_OFF + 512);
    if (tid < 128) {
        dp_s[tid] = g_dp[b * 1024 + nt * 128 + tid];
        v_s[tid]  = v[nt * 128 + tid];
    }

    const int arow = mt * 128;
    const int brow = nt * 128;
    const int r_  = tid >> 1;                  // 0..127
    const int c0_ = (tid & 1) * 4;             // 0 or 4

    // prologue: stages 0,1
    #pragma unroll
    for (int s = 0; s < 2; s++) {
        uint32_t st = smb + s * STAGE_BYTES;
        #pragma unroll
        for (int c = 0; c < 4; c++) {
            uint32_t off = SWZ128((uint32_t)(r_ * 128 + (c0_ + c) * 16));
            cp_async16(st + off,         &g_encH[(size_t)(arow + r_) * 1024 + s * 64 + (c0_ + c) * 8]);
            cp_async16(st + 16384 + off, &g_w1H[(size_t)(brow + r_) * 1024 + s * 64 + (c0_ + c) * 8]);
        }
        CP_COMMIT();
    }

    float acc[2][8][4];
    #pragma unroll
    for (int t = 0; t < 2; t++)
        #pragma unroll
        for (int j = 0; j < 8; j++)
            #pragma unroll
            for (int q = 0; q < 4; q++) acc[t][j][q] = 0.f;

    // ldmatrix lane addressing
    const int l15 = lane & 15, lh = lane >> 4;                       // A x4
    const int bn_row  = (lane & 7) + ((lane >> 4) << 3);             // B x4: row in n16
    const int bk_half = (lane >> 3) & 1;                             // B x4: k-half

    uint32_t afr[2][2][4];   // [kk-parity][m-tile][regs]
    uint32_t bfr[3][4];      // [u mod 3][regs] — distance-2 rotating buffer

#define LD_A(par, kk) do {                                                                         \
        ldsm_x4(afr[par][0], Ast + SWZ128((uint32_t)((warp_m * 32 +      l15) * 128 + (kk) * 32 + lh * 16))); \
        ldsm_x4(afr[par][1], Ast + SWZ128((uint32_t)((warp_m * 32 + 16 + l15) * 128 + (kk) * 32 + lh * 16))); \
    } while (0)
#define LD_B(slot, kk, c)                                                                          \
        ldsm_x4(bfr[slot], Bst + SWZ128((uint32_t)((warp_n * 64 + (c) * 16 + bn_row) * 128 + (kk) * 32 + bk_half * 16)))

    #pragma unroll 1
    for (int ks = 0; ks < 16; ks++) {
        CP_WAIT1();
        __syncthreads();   // single barrier per stage (prefetch dist 2 over 3 bufs)

        if (ks + 2 < 16) {
            const int s = ks + 2;
            uint32_t st = smb + (s % 3) * STAGE_BYTES;
            #pragma unroll
            for (int c = 0; c < 4; c++) {
                uint32_t off = SWZ128((uint32_t)(r_ * 128 + (c0_ + c) * 16));
                cp_async16(st + off,         &g_encH[(size_t)(arow + r_) * 1024 + s * 64 + (c0_ + c) * 8]);
                cp_async16(st + 16384 + off, &g_w1H[(size_t)(brow + r_) * 1024 + s * 64 + (c0_ + c) * 8]);
            }
        }
        CP_COMMIT();

        uint32_t Ast = smb + (ks % 3) * STAGE_BYTES;
        uint32_t Bst = Ast + 16384;

        // preload: A(kk=0), B frags for u=0 and u=1 (distance 2)
        LD_A(0, 0);
        LD_B(0, 0, 0);
        LD_B(1, 0, 1);
        #pragma unroll
        for (int u = 0; u < 16; u++) {
            const int kk = u >> 2, c = u & 3;
            if (u < 14) LD_B((u + 2) % 3, (u + 2) >> 2, (u + 2) & 3);  // B at distance 2
            if (c == 0 && kk < 3) LD_A((kk + 1) & 1, kk + 1);          // A for next kk
            const int p = kk & 1, q = u % 3;
            mma16816(acc[0][2 * c],     afr[p][0], bfr[q]);
            mma16816(acc[1][2 * c],     afr[p][1], bfr[q]);
            mma16816(acc[0][2 * c + 1], afr[p][0], bfr[q] + 2);
            mma16816(acc[1][2 * c + 1], afr[p][1], bfr[q] + 2);
        }
    }
#undef LD_A
#undef LD_B

    // fused epilogue: per-row sum of v[n]*tanh(acc + dp[n])
    #pragma unroll
    for (int t = 0; t < 2; t++) {
        float rs0 = 0.f, rs1 = 0.f;     // rows m_base, m_base+8
        #pragma unroll
        for (int j = 0; j < 8; j++) {
            int nl = warp_n * 64 + j * 8 + (lane & 3) * 2;
            float d0 = dp_s[nl], d1 = dp_s[nl + 1];
            float v0 = v_s[nl],  v1 = v_s[nl + 1];
            float y0, y1, y2, y3;
            asm("tanh.approx.f32 %0, %1;" : "=f"(y0) : "f"(acc[t][j][0] + d0));
            asm("tanh.approx.f32 %0, %1;" : "=f"(y1) : "f"(acc[t][j][1] + d1));
            asm("tanh.approx.f32 %0, %1;" : "=f"(y2) : "f"(acc[t][j][2] + d0));
            asm("tanh.approx.f32 %0, %1;" : "=f"(y3) : "f"(acc[t][j][3] + d1));
            rs0 += v0 * y0 + v1 * y1;
            rs1 += v0 * y2 + v1 * y3;
        }
        rs0 += __shfl_xor_sync(~0u, rs0, 1); rs0 += __shfl_xor_sync(~0u, rs0, 2);
        rs1 += __shfl_xor_sync(~0u, rs1, 1); rs1 += __shfl_xor_sync(~0u, rs1, 2);
        if ((lane & 3) == 0) {
            int m = mt * 128 + warp_m * 32 + t * 16 + (lane >> 2);
            int p = nt * 2 + warp_n;
            g_scores_part[p][m]     = rs0;
            g_scores_part[p][m + 8] = rs1;
        }
    }
}

// ============================================================
// 4. softmax over sequence dim (per batch)
// ============================================================
__global__ void softmax_kernel() {
    __shared__ float red[32];
    __shared__ float stat[2];
    int bq = blockIdx.x;
    int t = threadIdx.x, lane = t & 31, wid = t >> 5;   // 1024 threads
    int base = bq * 2048;
    float s0 = 0.f, s1 = 0.f;
    #pragma unroll
    for (int p = 0; p < NPART; p++) {
        s0 += g_scores_part[p][base + t];
        s1 += g_scores_part[p][base + 1024 + t];
    }
    float mx = fmaxf(s0, s1);
    #pragma unroll
    for (int o = 16; o > 0; o >>= 1) mx = fmaxf(mx, __shfl_xor_sync(~0u, mx, o));
    if (lane == 0) red[wid] = mx;
    __syncthreads();
    if (t < 32) {
        float m2 = red[t];
        #pragma unroll
        for (int o = 16; o > 0; o >>= 1) m2 = fmaxf(m2, __shfl_xor_sync(~0u, m2, o));
        if (t == 0) stat[0] = m2;
    }
    __syncthreads();
    float M = stat[0];
    float e0 = __expf(s0 - M), e1 = __expf(s1 - M);
    float sum = e0 + e1;
    #pragma unroll
    for (int o = 16; o > 0; o >>= 1) sum += __shfl_xor_sync(~0u, sum, o);
    if (lane == 0) red[wid] = sum;
    __syncthreads();
    if (t < 32) {
        float z = red[t];
        #pragma unroll
        for (int o = 16; o > 0; o >>= 1) z += __shfl_xor_sync(~0u, z, o);
        if (t == 0) stat[1] = z;
    }
    __syncthreads();
    float inv = 1.f / stat[1];
    g_attn[base + t]        = e0 * inv;
    g_attn[base + 1024 + t] = e1 * inv;
}

// ============================================================
// 5. context partials over s-chunks (fp16 enc, half2 loads)
// ============================================================
__global__ void context_kernel() {
    __shared__ float attn_s[128];
    int sc = blockIdx.x, eb = blockIdx.y, b = blockIdx.z;   // 16 x 4 x 32
    int t = threadIdx.x;                  // 128
    attn_s[t] = g_attn[b * 2048 + sc * 128 + t];
    __syncthreads();
    int e2 = eb * 256 + 2 * t;            // even element index
    const __half2* base = (const __half2*)g_encH
        + ((size_t)(b * 2048 + sc * 128) * 1024 + e2) / 2;
    float acc0 = 0.f, acc1 = 0.f;
    #pragma unroll 4
    for (int s = 0; s < 128; s++) {
        __half2 h = base[(size_t)s * 512];
        float2 f = __half22float2(h);
        acc0 += attn_s[s] * f.x;
        acc1 += attn_s[s] * f.y;
    }
    g_ctx_part[sc][b * 1024 + e2]     = acc0;
    g_ctx_part[sc][b * 1024 + e2 + 1] = acc1;
}

// ============================================================
// 6. final reduce -> d_out [32,1024] fp32
// ============================================================
__global__ void reduce_kernel(float* __restrict__ out) {
    int i = blockIdx.x * 256 + threadIdx.x;   // 128 x 256
    float acc = 0.f;
    #pragma unroll
    for (int sc = 0; sc < 16; sc++) acc += g_ctx_part[sc][i];
    out[i] = acc;
}

// ============================================================
extern "C" void kernel_launch(void* const* d_in, const int* in_sizes, int n_in,
                              void* d_out, int out_size) {
    const float* enc = (const float*)d_in[0];
    const float* dec = (const float*)d_in[1];
    const float* w1  = (const float*)d_in[2];
    const float* b1  = (const float*)d_in[3];
    const float* w2  = (const float*)d_in[4];
    const float* b2  = (const float*)d_in[5];
    const float* v   = (const float*)d_in[6];
    // bv (d_in[7]) unused: softmax is shift-invariant.
    float* out = (float*)d_out;

    cudaFuncSetAttribute(gemm_kernel, cudaFuncAttributeMaxDynamicSharedMemorySize, SMEM_REQ);

    conv_enc_kernel<<<8192, 256>>>(enc);
    conv_w1_kernel<<<dim3(32, 32), dim3(32, 8)>>>(w1);
    dp_kernel<<<256, 128>>>(dec, w2, b1, b2);
    gemm_kernel<<<4096, 256, SMEM_REQ>>>(v);
    softmax_kernel<<<32, 1024>>>();
    context_kernel<<<dim3(16, 4, 32), 128>>>();
    reduce_kernel<<<128, 256>>>(out);
}

// round 11
// speedup vs baseline: 1.4263x; 1.0377x over previous
#include <cuda_runtime.h>
#include <cuda_fp16.h>
#include <cstdint>

// ============================================================
// Bahdanau additive attention, GB300 sm_103 (baseline PTX only)
//   dp[b,e]  = dec[b]@w2 + b2 + b1
//   scores   = v . tanh(enc@w1 + dp)     (fused HMMA mma.sync GEMM epilogue)
//   attn     = softmax_s(scores)         (bv dropped: shift-invariant)
//   context  = attn @ enc                (fp16 enc)
// ============================================================

#define ENCD 1024
#define NB   32
#define NS   2048
#define MTOT (NB*NS)

// GEMM tile: BM=128, BN=128, BK=64, 3-stage cp.async, 256 thr (8 warps 4x2)
#define STAGE_BYTES 32768          // A 16KB + B 16KB
#define MISC_OFF    (3*STAGE_BYTES)
#define SMEM_REQ    (MISC_OFF + 2048)
#define NPART 16                   // 8 nt * 2 warp_n partial score slots

// ---------------- device scratch ----------------
__device__ __half g_encH[(size_t)MTOT*ENCD];      // enc fp16, 128MB
__device__ __half g_w1H[(size_t)ENCD*ENCD];       // w1 transposed: [e][d]
__device__ float  g_dp[NB*ENCD];
__device__ float  g_scores_part[NPART][MTOT];     // 4MB
__device__ float  g_attn[NB*NS];
__device__ float  g_ctx_part[16][NB*ENCD];

// ---------------- helpers ----------------
__device__ __forceinline__ uint32_t smem_u32(const void* p) {
    uint32_t a;
    asm("{ .reg .u64 t; cvta.to.shared.u64 t, %1; cvt.u32.u64 %0, t; }" : "=r"(a) : "l"(p));
    return a;
}
#define SWZ128(off) ((off) ^ (((off) >> 3) & 0x70))

__device__ __forceinline__ void cp_async16(uint32_t dst, const void* src) {
    asm volatile("cp.async.cg.shared.global [%0], [%1], 16;" :: "r"(dst), "l"(src) : "memory");
}
#define CP_COMMIT() asm volatile("cp.async.commit_group;" ::: "memory")
#define CP_WAIT0()  asm volatile("cp.async.wait_group 0;" ::: "memory")

__device__ __forceinline__ void ldsm_x4(uint32_t* r, uint32_t addr) {
    asm volatile("ldmatrix.sync.aligned.m8n8.x4.shared.b16 {%0,%1,%2,%3}, [%4];"
                 : "=r"(r[0]), "=r"(r[1]), "=r"(r[2]), "=r"(r[3]) : "r"(addr));
}
__device__ __forceinline__ void mma16816(float* c, const uint32_t* a, const uint32_t* b) {
    asm volatile(
        "mma.sync.aligned.m16n8k16.row.col.f32.f16.f16.f32 "
        "{%0,%1,%2,%3}, {%4,%5,%6,%7}, {%8,%9}, {%0,%1,%2,%3};"
        : "+f"(c[0]), "+f"(c[1]), "+f"(c[2]), "+f"(c[3])
        : "r"(a[0]), "r"(a[1]), "r"(a[2]), "r"(a[3]), "r"(b[0]), "r"(b[1]));
}

// ============================================================
// 1a. enc fp32 -> fp16
// ============================================================
__global__ void conv_enc_kernel(const float* __restrict__ enc) {
    const float4* in4 = (const float4*)enc;
    uint4* out4 = (uint4*)g_encH;
    int base = blockIdx.x * 256 + threadIdx.x;           // 8192 blocks
    #pragma unroll
    for (int it = 0; it < 4; it++) {
        int o = base + it * 2097152;                     // 8388608 uint4 outs
        float4 a = in4[2 * o];
        float4 b = in4[2 * o + 1];
        __half2 h0 = __floats2half2_rn(a.x, a.y);
        __half2 h1 = __floats2half2_rn(a.z, a.w);
        __half2 h2 = __floats2half2_rn(b.x, b.y);
        __half2 h3 = __floats2half2_rn(b.z, b.w);
        uint4 r;
        r.x = *(const uint32_t*)&h0; r.y = *(const uint32_t*)&h1;
        r.z = *(const uint32_t*)&h2; r.w = *(const uint32_t*)&h3;
        out4[o] = r;
    }
}

// ============================================================
// 1b. w1 transpose -> fp16   g_w1H[e][d] = w1[d][e]
// ============================================================
__global__ void conv_w1_kernel(const float* __restrict__ w1) {
    __shared__ float tile[32][33];
    int dt = blockIdx.x * 32, et = blockIdx.y * 32;
    int tx = threadIdx.x, ty = threadIdx.y;               // 32x8
    #pragma unroll
    for (int i = 0; i < 4; i++)
        tile[ty + i * 8][tx] = w1[(dt + ty + i * 8) * 1024 + et + tx];
    __syncthreads();
    #pragma unroll
    for (int i = 0; i < 4; i++)
        g_w1H[(et + ty + i * 8) * 1024 + dt + tx] = __float2half(tile[tx][ty + i * 8]);
}

// ============================================================
// 2. dp[b][e] = dec[b]@w2 + b2[e] + b1[e]
// ============================================================
__global__ void dp_kernel(const float* __restrict__ dec, const float* __restrict__ w2,
                          const float* __restrict__ b1, const float* __restrict__ b2) {
    __shared__ float dec_s[1024];
    int b  = blockIdx.x >> 3;
    int eb = blockIdx.x & 7;
    int t  = threadIdx.x;       // 128
    #pragma unroll
    for (int i = 0; i < 8; i++) dec_s[t + i * 128] = dec[b * 1024 + t + i * 128];
    __syncthreads();
    int e = eb * 128 + t;
    float acc = 0.f;
    #pragma unroll 8
    for (int d = 0; d < 1024; d++)
        acc += dec_s[d] * w2[d * 1024 + e];
    g_dp[b * 1024 + e] = acc + b1[e] + b2[e];
}

// ============================================================
// 3. Fused GEMM + tanh + v-dot
//    mma.sync fp16, cp.async 3-stage, single barrier per stage,
//    4-slot B frag ring + cross-stage fragment preload (wait_group 0)
//    grid: 512 mt x 8 nt ; block 256 (8 warps, 4m x 2n, warp tile 32x64)
// ============================================================
__global__ void __launch_bounds__(256, 2)
gemm_kernel(const float* __restrict__ v) {
    extern __shared__ char sm[];
    uint32_t smb = smem_u32(sm);

    const int tid = threadIdx.x;
    const int lane = tid & 31, wid = tid >> 5;
    const int warp_m = wid >> 1, warp_n = wid & 1;        // 4 x 2
    const int mt = blockIdx.x >> 3;                        // 512
    const int nt = blockIdx.x & 7;                         // 8
    const int b  = mt >> 4;

    float* dp_s = (float*)(sm + MISC_OFF);
    float* v_s  = (float*)(sm + MISC_OFF + 512);
    if (tid < 128) {
        dp_s[tid] = g_dp[b * 1024 + nt * 128 + tid];
        v_s[tid]  = v[nt * 128 + tid];
    }

    const int arow = mt * 128;
    const int brow = nt * 128;
    const int r_  = tid >> 1;                  // 0..127
    const int c0_ = (tid & 1) * 4;             // 0 or 4

    // prologue: stages 0,1
    #pragma unroll
    for (int s = 0; s < 2; s++) {
        uint32_t st = smb + s * STAGE_BYTES;
        #pragma unroll
        for (int c = 0; c < 4; c++) {
            uint32_t off = SWZ128((uint32_t)(r_ * 128 + (c0_ + c) * 16));
            cp_async16(st + off,         &g_encH[(size_t)(arow + r_) * 1024 + s * 64 + (c0_ + c) * 8]);
            cp_async16(st + 16384 + off, &g_w1H[(size_t)(brow + r_) * 1024 + s * 64 + (c0_ + c) * 8]);
        }
        CP_COMMIT();
    }

    float acc[2][8][4];
    #pragma unroll
    for (int t = 0; t < 2; t++)
        #pragma unroll
        for (int j = 0; j < 8; j++)
            #pragma unroll
            for (int q = 0; q < 4; q++) acc[t][j][q] = 0.f;

    // ldmatrix lane addressing
    const int l15 = lane & 15, lh = lane >> 4;                       // A x4
    const int bn_row  = (lane & 7) + ((lane >> 4) << 3);             // B x4: row in n16
    const int bk_half = (lane >> 3) & 1;                             // B x4: k-half

    uint32_t afr[2][2][4];   // [kk-parity][m-tile][regs]
    uint32_t bfr[4][4];      // [u & 3][regs] — stage-periodic 4-slot ring, distance 2

#define LD_A(ast, par, kk) do {                                                                    \
        ldsm_x4(afr[par][0], (ast) + SWZ128((uint32_t)((warp_m * 32 +      l15) * 128 + (kk) * 32 + lh * 16))); \
        ldsm_x4(afr[par][1], (ast) + SWZ128((uint32_t)((warp_m * 32 + 16 + l15) * 128 + (kk) * 32 + lh * 16))); \
    } while (0)
#define LD_B(bst, slot, kk, c)                                                                     \
        ldsm_x4(bfr[slot], (bst) + SWZ128((uint32_t)((warp_n * 64 + (c) * 16 + bn_row) * 128 + (kk) * 32 + bk_half * 16)))

    #pragma unroll 1
    for (int ks = 0; ks < 16; ks++) {
        CP_WAIT0();          // all landed: buffers ks%3 and (ks+1)%3 both valid
        __syncthreads();     // readers of buffer (ks+2)%3 (stage ks-1) are done

        if (ks + 2 < 16) {
            const int s = ks + 2;
            uint32_t st = smb + (s % 3) * STAGE_BYTES;
            #pragma unroll
            for (int c = 0; c < 4; c++) {
                uint32_t off = SWZ128((uint32_t)(r_ * 128 + (c0_ + c) * 16));
                cp_async16(st + off,         &g_encH[(size_t)(arow + r_) * 1024 + s * 64 + (c0_ + c) * 8]);
                cp_async16(st + 16384 + off, &g_w1H[(size_t)(brow + r_) * 1024 + s * 64 + (c0_ + c) * 8]);
            }
        }
        CP_COMMIT();

        uint32_t Ast  = smb + (ks % 3) * STAGE_BYTES;
        uint32_t Bst  = Ast + 16384;
        uint32_t NAst = smb + ((ks + 1) % 3) * STAGE_BYTES;   // next stage (data already landed)
        uint32_t NBst = NAst + 16384;

        if (ks == 0) {       // only the first stage pays the startup chain
            LD_A(Ast, 0, 0);
            LD_B(Bst, 0, 0, 0);
            LD_B(Bst, 1, 0, 1);
        }

        #pragma unroll
        for (int u = 0; u < 16; u++) {
            const int kk = u >> 2, c = u & 3;
            // B prefetch at distance 2; slots are stage-periodic (16 % 4 == 0)
            if (u < 14)       LD_B(Bst,  (u + 2) & 3, (u + 2) >> 2, (u + 2) & 3);
            else if (ks < 15) LD_B(NBst, (u + 2) & 3, 0,            (u + 2) & 3);  // next stage kk=0, c=0/1
            if (c == 0) {
                if (kk < 3)        LD_A(Ast,  (kk + 1) & 1, kk + 1);
                else if (ks < 15)  LD_A(NAst, 0,            0);                     // next stage kk=0
            }
            const int p = kk & 1, q = u & 3;
            mma16816(acc[0][2 * c],     afr[p][0], bfr[q]);
            mma16816(acc[1][2 * c],     afr[p][1], bfr[q]);
            mma16816(acc[0][2 * c + 1], afr[p][0], bfr[q] + 2);
            mma16816(acc[1][2 * c + 1], afr[p][1], bfr[q] + 2);
        }
    }
#undef LD_A
#undef LD_B

    // fused epilogue: per-row sum of v[n]*tanh(acc + dp[n])
    #pragma unroll
    for (int t = 0; t < 2; t++) {
        float rs0 = 0.f, rs1 = 0.f;     // rows m_base, m_base+8
        #pragma unroll
        for (int j = 0; j < 8; j++) {
            int nl = warp_n * 64 + j * 8 + (lane & 3) * 2;
            float d0 = dp_s[nl], d1 = dp_s[nl + 1];
            float v0 = v_s[nl],  v1 = v_s[nl + 1];
            float y0, y1, y2, y3;
            asm("tanh.approx.f32 %0, %1;" : "=f"(y0) : "f"(acc[t][j][0] + d0));
            asm("tanh.approx.f32 %0, %1;" : "=f"(y1) : "f"(acc[t][j][1] + d1));
            asm("tanh.approx.f32 %0, %1;" : "=f"(y2) : "f"(acc[t][j][2] + d0));
            asm("tanh.approx.f32 %0, %1;" : "=f"(y3) : "f"(acc[t][j][3] + d1));
            rs0 += v0 * y0 + v1 * y1;
            rs1 += v0 * y2 + v1 * y3;
        }
        rs0 += __shfl_xor_sync(~0u, rs0, 1); rs0 += __shfl_xor_sync(~0u, rs0, 2);
        rs1 += __shfl_xor_sync(~0u, rs1, 1); rs1 += __shfl_xor_sync(~0u, rs1, 2);
        if ((lane & 3) == 0) {
            int m = mt * 128 + warp_m * 32 + t * 16 + (lane >> 2);
            int p = nt * 2 + warp_n;
            g_scores_part[p][m]     = rs0;
            g_scores_part[p][m + 8] = rs1;
        }
    }
}

// ============================================================
// 4. softmax over sequence dim (per batch)
// ============================================================
__global__ void softmax_kernel() {
    __shared__ float red[32];
    __shared__ float stat[2];
    int bq = blockIdx.x;
    int t = threadIdx.x, lane = t & 31, wid = t >> 5;   // 1024 threads
    int base = bq * 2048;
    float s0 = 0.f, s1 = 0.f;
    #pragma unroll
    for (int p = 0; p < NPART; p++) {
        s0 += g_scores_part[p][base + t];
        s1 += g_scores_part[p][base + 1024 + t];
    }
    float mx = fmaxf(s0, s1);
    #pragma unroll
    for (int o = 16; o > 0; o >>= 1) mx = fmaxf(mx, __shfl_xor_sync(~0u, mx, o));
    if (lane == 0) red[wid] = mx;
    __syncthreads();
    if (t < 32) {
        float m2 = red[t];
        #pragma unroll
        for (int o = 16; o > 0; o >>= 1) m2 = fmaxf(m2, __shfl_xor_sync(~0u, m2, o));
        if (t == 0) stat[0] = m2;
    }
    __syncthreads();
    float M = stat[0];
    float e0 = __expf(s0 - M), e1 = __expf(s1 - M);
    float sum = e0 + e1;
    #pragma unroll
    for (int o = 16; o > 0; o >>= 1) sum += __shfl_xor_sync(~0u, sum, o);
    if (lane == 0) red[wid] = sum;
    __syncthreads();
    if (t < 32) {
        float z = red[t];
        #pragma unroll
        for (int o = 16; o > 0; o >>= 1) z += __shfl_xor_sync(~0u, z, o);
        if (t == 0) stat[1] = z;
    }
    __syncthreads();
    float inv = 1.f / stat[1];
    g_attn[base + t]        = e0 * inv;
    g_attn[base + 1024 + t] = e1 * inv;
}

// ============================================================
// 5. context partials over s-chunks (fp16 enc, half2 loads)
// ============================================================
__global__ void context_kernel() {
    __shared__ float attn_s[128];
    int sc = blockIdx.x, eb = blockIdx.y, b = blockIdx.z;   // 16 x 4 x 32
    int t = threadIdx.x;                  // 128
    attn_s[t] = g_attn[b * 2048 + sc * 128 + t];
    __syncthreads();
    int e2 = eb * 256 + 2 * t;            // even element index
    const __half2* base = (const __half2*)g_encH
        + ((size_t)(b * 2048 + sc * 128) * 1024 + e2) / 2;
    float acc0 = 0.f, acc1 = 0.f;
    #pragma unroll 4
    for (int s = 0; s < 128; s++) {
        __half2 h = base[(size_t)s * 512];
        float2 f = __half22float2(h);
        acc0 += attn_s[s] * f.x;
        acc1 += attn_s[s] * f.y;
    }
    g_ctx_part[sc][b * 1024 + e2]     = acc0;
    g_ctx_part[sc][b * 1024 + e2 + 1] = acc1;
}

// ============================================================
// 6. final reduce -> d_out [32,1024] fp32
// ============================================================
__global__ void reduce_kernel(float* __restrict__ out) {
    int i = blockIdx.x * 256 + threadIdx.x;   // 128 x 256
    float acc = 0.f;
    #pragma unroll
    for (int sc = 0; sc < 16; sc++) acc += g_ctx_part[sc][i];
    out[i] = acc;
}

// ============================================================
extern "C" void kernel_launch(void* const* d_in, const int* in_sizes, int n_in,
                              void* d_out, int out_size) {
    const float* enc = (const float*)d_in[0];
    const float* dec = (const float*)d_in[1];
    const float* w1  = (const float*)d_in[2];
    const float* b1  = (const float*)d_in[3];
    const float* w2  = (const float*)d_in[4];
    const float* b2  = (const float*)d_in[5];
    const float* v   = (const float*)d_in[6];
    // bv (d_in[7]) unused: softmax is shift-invariant.
    float* out = (float*)d_out;

    // created once on the (uncaptured) correctness call, reused under capture
    static cudaStream_t s2 = [] {
        cudaStream_t s; cudaStreamCreateWithFlags(&s, cudaStreamNonBlocking); return s;
    }();
    static cudaEvent_t ev_fork = [] {
        cudaEvent_t e; cudaEventCreateWithFlags(&e, cudaEventDisableTiming); return e;
    }();
    static cudaEvent_t ev_join = [] {
        cudaEvent_t e; cudaEventCreateWithFlags(&e, cudaEventDisableTiming); return e;
    }();

    cudaFuncSetAttribute(gemm_kernel, cudaFuncAttributeMaxDynamicSharedMemorySize, SMEM_REQ);

    // fork: w1-transpose + dec-projection run concurrent with enc fp16 convert
    cudaEventRecord(ev_fork, 0);
    cudaStreamWaitEvent(s2, ev_fork, 0);
    conv_w1_kernel<<<dim3(32, 32), dim3(32, 8), 0, s2>>>(w1);
    dp_kernel<<<256, 128, 0, s2>>>(dec, w2, b1, b2);
    cudaEventRecord(ev_join, s2);

    conv_enc_kernel<<<8192, 256>>>(enc);

    cudaStreamWaitEvent(0, ev_join, 0);   // join before GEMM consumes w1H/dp
    gemm_kernel<<<4096, 256, SMEM_REQ>>>(v);
    softmax_kernel<<<32, 1024>>>();
    context_kernel<<<dim3(16, 4, 32), 128>>>();
    reduce_kernel<<<128, 256>>>(out);
}